// round 16
// baseline (speedup 1.0000x reference)
#include <cuda_runtime.h>
#include <cstdint>
#include <math_constants.h>

#define BATCH 131072
#define RPB   256              /* rows per CTA (narrow gemm) */
#define NPB   (BATCH / RPB)    /* 512 row blocks (narrow) */
#define NPB2  1024             /* 128-row blocks (wide gemm) */

#if defined(__CUDA_ARCH_FEAT_SM103_ALL) || defined(__CUDA_ARCH_FEAT_SM100_ALL) || defined(__CUDA_ARCH_FEAT_SM101_ALL)
#define HAS_TCGEN05 1
#else
#define HAS_TCGEN05 0
#endif

// ---------------- scratch ----------------------------------------------------
__device__ float g_a1[BATCH * 128];
__device__ float g_a2[BATCH * 256];
__device__ float g_a3[BATCH * 128];
__device__ float g_psum[256 * NPB2];  // column-major: [col][rowblock]
__device__ float g_psq [256 * NPB2];
__device__ float g_scale[256];
__device__ float g_shift[256];
__device__ float g_wtiles[147456];    // preformatted W tiles (8192 floats each)

// ---------------- ptx helpers -------------------------------------------------
__device__ __forceinline__ uint32_t smem_u32(const void* p) {
    uint32_t a;
    asm("{ .reg .u64 t; cvta.to.shared.u64 t, %1; cvt.u32.u64 %0, t; }" : "=r"(a) : "l"(p));
    return a;
}

#if HAS_TCGEN05
__device__ __forceinline__ uint32_t elect1() {
    uint32_t p;
    asm volatile("{\n\t.reg .pred p;\n\telect.sync _|p, 0xFFFFFFFF;\n\tselp.b32 %0, 1, 0, p;\n\t}" : "=r"(p));
    return p;
}
#define TCGEN05_ALLOC(smem_addr, nCols) \
    asm volatile("tcgen05.alloc.cta_group::1.sync.aligned.shared::cta.b32 [%0], %1;" \
                 :: "r"((uint32_t)(smem_addr)), "r"((uint32_t)(nCols)) : "memory")
#define TCGEN05_DEALLOC(tmem_addr, nCols) \
    asm volatile("tcgen05.dealloc.cta_group::1.sync.aligned.b32 %0, %1;" \
                 :: "r"(tmem_addr), "r"((uint32_t)(nCols)))
#define TCGEN05_RELINQ() \
    asm volatile("tcgen05.relinquish_alloc_permit.cta_group::1.sync.aligned;")
#define TCGEN05_COMMIT(mbar_smem_addr) \
    asm volatile("tcgen05.commit.cta_group::1.mbarrier::arrive::one.shared::cluster.b64 [%0];" \
                 :: "r"((uint32_t)(mbar_smem_addr)) : "memory")
#define TCGEN05_FENCE_AFTER() \
    asm volatile("tcgen05.fence::after_thread_sync;" ::: "memory")
#define TCGEN05_FENCE_BEFORE() \
    asm volatile("tcgen05.fence::before_thread_sync;" ::: "memory")
#define TCGEN05_WAIT_LD() \
    asm volatile("tcgen05.wait::ld.sync.aligned;" ::: "memory")
#define MBARRIER_INIT(mbar_smem_addr, count) \
    asm volatile("mbarrier.init.shared.b64 [%0], %1;" \
                 :: "r"((uint32_t)(mbar_smem_addr)), "r"((uint32_t)(count)) : "memory")
#define MBARRIER_WAIT_PARITY(mbar_smem_addr, phase_parity) do { \
    uint32_t _mbar = (uint32_t)(mbar_smem_addr); \
    uint32_t _parity = (uint32_t)(phase_parity); \
    uint32_t _done; \
    asm volatile("{\n\t.reg .pred p;\n\t" \
        "mbarrier.try_wait.parity.acquire.cta.shared::cta.b64 p, [%1], %2;\n\t" \
        "selp.b32 %0, 1, 0, p;\n\t}" \
        : "=r"(_done) : "r"(_mbar), "r"(_parity) : "memory"); \
    if (!_done) { \
        asm volatile("{\n\t.reg .pred P1;\n\t" \
            "WAIT_LOOP_%=:\n\t" \
            "mbarrier.try_wait.parity.acquire.cta.shared::cta.b64 P1, [%0], %1, 0x989680;\n\t" \
            "@P1 bra.uni WAIT_DONE_%=;\n\t" \
            "bra.uni WAIT_LOOP_%=;\n\t" \
            "WAIT_DONE_%=:\n\t}" \
            :: "r"(_mbar), "r"(_parity) : "memory"); \
    } \
} while (0)
#define TCGEN05_LD_32X32B_X32(r, tmem_addr) \
    asm volatile("tcgen05.ld.sync.aligned.32x32b.x32.b32 " \
        "{%0, %1, %2, %3, %4, %5, %6, %7, " \
        " %8, %9, %10, %11, %12, %13, %14, %15, " \
        " %16, %17, %18, %19, %20, %21, %22, %23, " \
        " %24, %25, %26, %27, %28, %29, %30, %31}, [%32];" \
        : "=r"((r)[0]),  "=r"((r)[1]),  "=r"((r)[2]),  "=r"((r)[3]), \
          "=r"((r)[4]),  "=r"((r)[5]),  "=r"((r)[6]),  "=r"((r)[7]), \
          "=r"((r)[8]),  "=r"((r)[9]),  "=r"((r)[10]), "=r"((r)[11]), \
          "=r"((r)[12]), "=r"((r)[13]), "=r"((r)[14]), "=r"((r)[15]), \
          "=r"((r)[16]), "=r"((r)[17]), "=r"((r)[18]), "=r"((r)[19]), \
          "=r"((r)[20]), "=r"((r)[21]), "=r"((r)[22]), "=r"((r)[23]), \
          "=r"((r)[24]), "=r"((r)[25]), "=r"((r)[26]), "=r"((r)[27]), \
          "=r"((r)[28]), "=r"((r)[29]), "=r"((r)[30]), "=r"((r)[31]) \
        : "r"(tmem_addr))

__device__ __forceinline__ uint64_t sdesc(uint32_t addr) {
    return ((uint64_t)2 << 61) | ((uint64_t)1 << 46) | ((uint64_t)64 << 32) |
           ((uint64_t)1 << 16) | ((uint64_t)(addr >> 4) & 0x3FFF);
}
__device__ __forceinline__ void mma_tf32_ss(uint32_t d, uint64_t ad, uint64_t bd,
                                            uint32_t idesc, uint32_t en) {
    asm volatile("{\n\t.reg .pred p;\n\tsetp.ne.u32 p, %4, 0;\n\t"
        "tcgen05.mma.cta_group::1.kind::tf32 [%0], %1, %2, %3, {%5, %5, %5, %5}, p;\n\t}"
        :: "r"(d), "l"(ad), "l"(bd), "r"(idesc), "r"(en), "r"(0u) : "memory");
}
#endif // HAS_TCGEN05

#define SW128(o) ((o) ^ (((o) >> 3) & 0x70))

#define STAGE_SZ 98304
#define GEMM_SMEM (216 * 1024)
#define IDESC_TF32 ((1u << 4) | (2u << 7) | (2u << 10) | (16u << 17) | (8u << 24))

// ---------------------------------------------------------------------------
// prep_all: one launch formats all W tiles (tf32 hi/lo split, SW128 image).
// ---------------------------------------------------------------------------
__global__ void prep_all(const float* __restrict__ W1, const float* __restrict__ W2,
                         const float* __restrict__ W3, float* __restrict__ wt)
{
    const int b = blockIdx.x;
    const float* W; float* dst; int Kdim, N, ch, cb, NCH;
    if (b < 2)       { W = W1; dst = wt;         Kdim = 50;  N = 128; NCH = 2; ch = b;             cb = 0; }
    else if (b < 10) { W = W2; dst = wt + 16384; Kdim = 128; N = 256; NCH = 4; ch = (b - 2) & 3;   cb = (b - 2) >> 2; }
    else             { W = W3; dst = wt + 81920; Kdim = 256; N = 128; NCH = 8; ch = b - 10;        cb = 0; }

    char* tile = (char*)(dst + (size_t)(cb * NCH + ch) * 8192);
    const int tid = threadIdx.x;
#pragma unroll
    for (int e = 0; e < 16; e++) {
        int idx = tid + e * 256;
        int n = idx >> 5, kk = idx & 31;
        int k = ch * 32 + kk;
        float v = (k < Kdim) ? W[(size_t)k * N + cb * 128 + n] : 0.f;
        uint32_t hb; asm("cvt.rna.tf32.f32 %0, %1;" : "=r"(hb) : "f"(v));
        float lo = v - __uint_as_float(hb);
        uint32_t off = SW128((uint32_t)(n * 128 + kk * 4));
        *(uint32_t*)(tile + off)         = hb;
        *(float*)   (tile + 16384 + off) = lo;
    }
}

// ---------------------------------------------------------------------------
// Narrow GEMM: M=256/CTA, N=128. Layers 1 & 3. 2-deep A register prefetch.
// ---------------------------------------------------------------------------
template<int KDIM, bool ACT>
__global__ __launch_bounds__(512, 1)
void gemm_tc(const float* __restrict__ A, const float* __restrict__ W,
             const float* __restrict__ wt, const float* __restrict__ bias,
             float* __restrict__ C, int N)
{
#if HAS_TCGEN05
    constexpr int NCH = (KDIM + 31) / 32;
    extern __shared__ char dsm[];
    const uint32_t sb0 = smem_u32(dsm);
    const uint32_t pad = ((sb0 + 1023) & ~1023u) - sb0;
    char* bp = dsm + pad;
    const uint32_t sbu = sb0 + pad;

    float* sSc  = (float*)(bp + 196608);
    float* sSh  = (float*)(bp + 197632);
    float* sB   = (float*)(bp + 198656);
    float* redS = (float*)(bp + 199680);
    float* redQ = (float*)(bp + 207872);

    __shared__ uint64_t s_mbar[2];
    __shared__ uint32_t s_tptr;
    const uint32_t mbA[2] = { smem_u32(&s_mbar[0]), smem_u32(&s_mbar[1]) };

    const int tid  = threadIdx.x;
    const int wid  = tid >> 5;
    const int lane = tid & 31;
    const int row0 = blockIdx.x * RPB;
    const int col0 = blockIdx.y * 128;

    if (ACT) {
        for (int i = tid; i < KDIM; i += 512) { sSc[i] = g_scale[i]; sSh[i] = g_shift[i]; }
    }
    for (int i = tid; i < 128; i += 512) sB[i] = bias[col0 + i];
    if (tid == 0) { MBARRIER_INIT(mbA[0], 1); MBARRIER_INIT(mbA[1], 1); }
    if (wid == 0) TCGEN05_ALLOC(smem_u32(&s_tptr), 256);
    __syncthreads();
    const uint32_t tmem = s_tptr;

    const int pkq = tid & 7;
    float4 pre[4], pre2[4];
    if (KDIM % 4 == 0) {
#pragma unroll
        for (int t = 0; t < 2; t++)
#pragma unroll
            for (int e = 0; e < 2; e++) {
                int m = (tid + e * 512) >> 3;
                pre[t * 2 + e] = *(const float4*)(A + (size_t)(row0 + t * 128 + m) * KDIM + pkq * 4);
            }
        if (NCH > 1) {
#pragma unroll
            for (int t = 0; t < 2; t++)
#pragma unroll
                for (int e = 0; e < 2; e++) {
                    int m = (tid + e * 512) >> 3;
                    pre2[t * 2 + e] = *(const float4*)(A + (size_t)(row0 + t * 128 + m) * KDIM + 32 + pkq * 4);
                }
        }
    }

    for (int ch = 0; ch < NCH; ch++) {
        const int st  = ch & 1;
        const int use = ch >> 1;
        if (use >= 1) { MBARRIER_WAIT_PARITY(mbA[st], (use - 1) & 1); }

        char* ps = bp + st * STAGE_SZ;
        const int k0 = ch * 32;

        {
            const float4* src = (const float4*)(wt + (size_t)(blockIdx.y * NCH + ch) * 8192);
            const uint32_t dstA = sbu + st * STAGE_SZ + 65536;
#pragma unroll
            for (int i = 0; i < 4; i++) {
                asm volatile("cp.async.cg.shared.global [%0], [%1], 16;"
                             :: "r"(dstA + (uint32_t)(tid + i * 512) * 16),
                                "l"(src + tid + i * 512) : "memory");
            }
            asm volatile("cp.async.commit_group;" ::: "memory");
        }

        // prefetch A regs for chunk ch+2 (LDG issue only; 2-deep pipeline)
        float4 nxt[4];
        if (KDIM % 4 == 0 && ch + 2 < NCH) {
            const int k2 = (ch + 2) * 32;
#pragma unroll
            for (int t = 0; t < 2; t++)
#pragma unroll
                for (int e = 0; e < 2; e++) {
                    int m = (tid + e * 512) >> 3;
                    nxt[t * 2 + e] = *(const float4*)(A + (size_t)(row0 + t * 128 + m) * KDIM + k2 + pkq * 4);
                }
        }

        if (KDIM % 4 == 0) {
#pragma unroll
            for (int t = 0; t < 2; t++) {
                char* pAh = ps + t * 32768;
                char* pAl = pAh + 16384;
#pragma unroll
                for (int e = 0; e < 2; e++) {
                    int m = (tid + e * 512) >> 3;
                    float4 v4 = pre[t * 2 + e];
                    float vv[4] = {v4.x, v4.y, v4.z, v4.w};
                    uint32_t hi[4]; float lo[4];
#pragma unroll
                    for (int u = 0; u < 4; u++) {
                        float v = vv[u];
                        if (ACT) {
                            int k = k0 + pkq * 4 + u;
                            v = fmaf(v, sSc[k], sSh[k]);
                            v = v > 0.f ? v : 0.2f * v;
                        }
                        asm("cvt.rna.tf32.f32 %0, %1;" : "=r"(hi[u]) : "f"(v));
                        lo[u] = v - __uint_as_float(hi[u]);
                    }
                    uint32_t off = SW128((uint32_t)(m * 128 + pkq * 16));
                    *(uint4*)(pAh + off)  = make_uint4(hi[0], hi[1], hi[2], hi[3]);
                    *(float4*)(pAl + off) = make_float4(lo[0], lo[1], lo[2], lo[3]);
                }
            }
        } else {
#pragma unroll
            for (int t = 0; t < 2; t++) {
                char* pAh = ps + t * 32768;
                char* pAl = pAh + 16384;
                const int rbase = row0 + t * 128;
#pragma unroll
                for (int i = 0; i < 8; i++) {
                    int idx = tid + i * 512;
                    int m = idx >> 5, kk = idx & 31, k = k0 + kk;
                    float v = 0.f;
                    if (k < KDIM) {
                        v = A[(size_t)(rbase + m) * KDIM + k];
                        if (ACT) {
                            v = fmaf(v, sSc[k], sSh[k]);
                            v = v > 0.f ? v : 0.2f * v;
                        }
                    }
                    uint32_t hb; asm("cvt.rna.tf32.f32 %0, %1;" : "=r"(hb) : "f"(v));
                    float lo = v - __uint_as_float(hb);
                    uint32_t off = SW128((uint32_t)(m * 128 + kk * 4));
                    *(uint32_t*)(pAh + off) = hb;
                    *(float*)   (pAl + off) = lo;
                }
            }
        }
        asm volatile("cp.async.wait_group 0;" ::: "memory");
        asm volatile("fence.proxy.async.shared::cta;" ::: "memory");
        __syncthreads();

        if (wid == 0 && elect1()) {
            const uint32_t sbase = sbu + st * STAGE_SZ;
            uint64_t bdh = sdesc(sbase + 65536), bdl = sdesc(sbase + 81920);
#pragma unroll
            for (int t = 0; t < 2; t++) {
                uint64_t adh = sdesc(sbase + t * 32768);
                uint64_t adl = sdesc(sbase + t * 32768 + 16384);
                uint32_t dofs = tmem + t * 128;
#pragma unroll
                for (int ks = 0; ks < 4; ks++) {
                    uint32_t en0 = (ch == 0 && ks == 0) ? 0u : 1u;
                    mma_tf32_ss(dofs, adh + ks * 2, bdh + ks * 2, IDESC_TF32, en0);
                    mma_tf32_ss(dofs, adh + ks * 2, bdl + ks * 2, IDESC_TF32, 1u);
                    mma_tf32_ss(dofs, adl + ks * 2, bdh + ks * 2, IDESC_TF32, 1u);
                }
            }
            TCGEN05_COMMIT(mbA[st]);
        }
#pragma unroll
        for (int i = 0; i < 4; i++) { pre[i] = pre2[i]; pre2[i] = nxt[i]; }
    }
    MBARRIER_WAIT_PARITY(mbA[(NCH - 1) & 1], ((NCH - 1) >> 1) & 1);
    TCGEN05_FENCE_AFTER();
    __syncthreads();

    {
        const int wg     = wid >> 2;
        const int rw     = wid & 3;
        const int wg_tid = tid & 127;
        const int t = wg >> 1, h = wg & 1;
        float* stage = (float*)(bp + wg * 36864);

#pragma unroll
        for (int half = 0; half < 2; half++) {
            uint32_t regs[32];
            TCGEN05_LD_32X32B_X32(regs, tmem + t * 128 + h * 64 + half * 32);
            TCGEN05_WAIT_LD();
            const int row = rw * 32 + lane;
#pragma unroll
            for (int j4 = 0; j4 < 8; j4++) {
                int cb = half * 32 + j4 * 4;
                float4 v = make_float4(
                    __uint_as_float(regs[j4 * 4 + 0]) + sB[h * 64 + cb + 0],
                    __uint_as_float(regs[j4 * 4 + 1]) + sB[h * 64 + cb + 1],
                    __uint_as_float(regs[j4 * 4 + 2]) + sB[h * 64 + cb + 2],
                    __uint_as_float(regs[j4 * 4 + 3]) + sB[h * 64 + cb + 3]);
                *(float4*)(stage + row * 68 + cb) = v;
            }
        }
        TCGEN05_FENCE_BEFORE();
        asm volatile("bar.sync %0, 128;" :: "r"(wg + 1) : "memory");

        const int cq = wg_tid & 15;
        const int rg = wg_tid >> 4;
        float sA[4] = {0.f, 0.f, 0.f, 0.f};
        float qA[4] = {0.f, 0.f, 0.f, 0.f};
#pragma unroll 4
        for (int it = 0; it < 16; it++) {
            int r = it * 8 + rg;
            float4 v = *(const float4*)(stage + r * 68 + cq * 4);
            *(float4*)&C[(size_t)(row0 + t * 128 + r) * N + col0 + h * 64 + cq * 4] = v;
            sA[0] += v.x; qA[0] = fmaf(v.x, v.x, qA[0]);
            sA[1] += v.y; qA[1] = fmaf(v.y, v.y, qA[1]);
            sA[2] += v.z; qA[2] = fmaf(v.z, v.z, qA[2]);
            sA[3] += v.w; qA[3] = fmaf(v.w, v.w, qA[3]);
        }
        *(float4*)&redS[(wg * 8 + rg) * 64 + cq * 4] = make_float4(sA[0], sA[1], sA[2], sA[3]);
        *(float4*)&redQ[(wg * 8 + rg) * 64 + cq * 4] = make_float4(qA[0], qA[1], qA[2], qA[3]);
        __syncthreads();
        if (tid < 128) {
            const int hh = tid >> 6, colin = tid & 63;
            float s = 0.f, q = 0.f;
#pragma unroll
            for (int tt = 0; tt < 2; tt++) {
                const int wgi = tt * 2 + hh;
#pragma unroll
                for (int rr = 0; rr < 8; rr++) {
                    s += redS[(wgi * 8 + rr) * 64 + colin];
                    q += redQ[(wgi * 8 + rr) * 64 + colin];
                }
            }
            int c = col0 + tid;
            g_psum[(size_t)c * NPB + blockIdx.x] = s;
            g_psq [(size_t)c * NPB + blockIdx.x] = q;
        }
    }

    __syncthreads();
    if (wid == 0) { TCGEN05_RELINQ(); TCGEN05_DEALLOC(tmem, 256); }

#else
    // FFMA fallback (plain sm_103 pass)
    extern __shared__ char dsm[];
    float (*As)[128] = (float(*)[128])dsm;
    float (*Ws)[128] = (float(*)[128])(dsm + 8192);
    float* sSc = (float*)(dsm + 16384);
    float* sSh = (float*)(dsm + 17408);

    const int tid  = threadIdx.x;
    const int col0 = blockIdx.y * 128;

    if (ACT) {
        for (int i = tid; i < KDIM; i += 512) { sSc[i] = g_scale[i]; sSh[i] = g_shift[i]; }
        __syncthreads();
    }
    const int ty = tid >> 4;
    const int tx = tid & 15;
    float bj[8];
#pragma unroll
    for (int j = 0; j < 8; j++) bj[j] = bias[col0 + tx * 8 + j];

    float cs[8], cq[8];
#pragma unroll
    for (int j = 0; j < 8; j++) { cs[j] = 0.f; cq[j] = 0.f; }

#pragma unroll 1
    for (int rt = 0; rt < 2; rt++) {
        const int row0 = blockIdx.x * RPB + rt * 128;
        float acc[4][8];
#pragma unroll
        for (int i = 0; i < 4; i++)
#pragma unroll
            for (int j = 0; j < 8; j++) acc[i][j] = 0.f;

        for (int k0 = 0; k0 < KDIM; k0 += 16) {
#pragma unroll
            for (int l = 0; l < 4; l++) {
                int idx = tid + l * 512;
                int m = idx >> 4, kk = idx & 15;
                int k = k0 + kk;
                float v = 0.f;
                if ((KDIM % 16 == 0) || k < KDIM) {
                    v = A[(size_t)(row0 + m) * KDIM + k];
                    if (ACT) {
                        v = fmaf(v, sSc[k], sSh[k]);
                        v = v > 0.f ? v : 0.2f * v;
                    }
                }
                As[kk][m] = v;
            }
#pragma unroll
            for (int l = 0; l < 4; l++) {
                int idx = tid + l * 512;
                int kk = idx >> 7, n = idx & 127;
                int k = k0 + kk;
                Ws[kk][n] = ((KDIM % 16 == 0) || k < KDIM) ? W[(size_t)k * N + col0 + n] : 0.f;
            }
            __syncthreads();
#pragma unroll
            for (int kk = 0; kk < 16; kk++) {
                float4 a0 = *(const float4*)&As[kk][ty * 4];
                float4 w0 = *(const float4*)&Ws[kk][tx * 8];
                float4 w1 = *(const float4*)&Ws[kk][tx * 8 + 4];
                float a[4] = {a0.x, a0.y, a0.z, a0.w};
                float w[8] = {w0.x, w0.y, w0.z, w0.w, w1.x, w1.y, w1.z, w1.w};
#pragma unroll
                for (int i = 0; i < 4; i++)
#pragma unroll
                    for (int j = 0; j < 8; j++)
                        acc[i][j] = fmaf(a[i], w[j], acc[i][j]);
            }
            __syncthreads();
        }
#pragma unroll
        for (int i = 0; i < 4; i++) {
            float v[8];
#pragma unroll
            for (int j = 0; j < 8; j++) {
                v[j] = acc[i][j] + bj[j];
                cs[j] += v[j];
                cq[j] = fmaf(v[j], v[j], cq[j]);
            }
            float* cptr = &C[(size_t)(row0 + ty * 4 + i) * N + col0 + tx * 8];
            *(float4*)cptr       = make_float4(v[0], v[1], v[2], v[3]);
            *(float4*)(cptr + 4) = make_float4(v[4], v[5], v[6], v[7]);
        }
        __syncthreads();
    }

    float* red = &As[0][0];
#pragma unroll
    for (int j = 0; j < 8; j++) red[ty * 128 + tx * 8 + j] = cs[j];
    __syncthreads();
    if (tid < 128) {
        float s = 0.f;
#pragma unroll
        for (int r = 0; r < 32; r++) s += red[r * 128 + tid];
        g_psum[(size_t)(col0 + tid) * NPB + blockIdx.x] = s;
    }
    __syncthreads();
#pragma unroll
    for (int j = 0; j < 8; j++) red[ty * 128 + tx * 8 + j] = cq[j];
    __syncthreads();
    if (tid < 128) {
        float s = 0.f;
#pragma unroll
        for (int r = 0; r < 32; r++) s += red[r * 128 + tid];
        g_psq[(size_t)(col0 + tid) * NPB + blockIdx.x] = s;
    }
#endif
}

// ---------------------------------------------------------------------------
// Wide GEMM (layer 2, R13): M=128, N=256 per CTA. A read ONCE; TMEM 256 cols.
// ---------------------------------------------------------------------------
__global__ __launch_bounds__(512, 1)
void gemm_wide(const float* __restrict__ A, const float* __restrict__ W,
               const float* __restrict__ wt, const float* __restrict__ bias,
               float* __restrict__ C)
{
    constexpr int KDIM = 128;
    constexpr int NCH  = 4;
    constexpr int N    = 256;
#if HAS_TCGEN05
    extern __shared__ char dsm[];
    const uint32_t sb0 = smem_u32(dsm);
    const uint32_t pad = ((sb0 + 1023) & ~1023u) - sb0;
    char* bp = dsm + pad;
    const uint32_t sbu = sb0 + pad;

    float* sSc  = (float*)(bp + 196608);
    float* sSh  = (float*)(bp + 197632);
    float* sB   = (float*)(bp + 198656);
    float* redS = (float*)(bp + 199680);
    float* redQ = (float*)(bp + 207872);

    __shared__ uint64_t s_mbar[2];
    __shared__ uint32_t s_tptr;
    const uint32_t mbA[2] = { smem_u32(&s_mbar[0]), smem_u32(&s_mbar[1]) };

    const int tid  = threadIdx.x;
    const int wid  = tid >> 5;
    const int lane = tid & 31;
    const int row0 = blockIdx.x * 128;

    for (int i = tid; i < KDIM; i += 512) { sSc[i] = g_scale[i]; sSh[i] = g_shift[i]; }
    for (int i = tid; i < 256; i += 512) sB[i] = bias[i];
    if (tid == 0) { MBARRIER_INIT(mbA[0], 1); MBARRIER_INIT(mbA[1], 1); }
    if (wid == 0) TCGEN05_ALLOC(smem_u32(&s_tptr), 256);
    __syncthreads();
    const uint32_t tmem = s_tptr;

    const int pkq = tid & 7;
    float4 pre[2], pre2[2];
#pragma unroll
    for (int e = 0; e < 2; e++) {
        int m = (tid + e * 512) >> 3;
        pre[e]  = *(const float4*)(A + (size_t)(row0 + m) * KDIM + pkq * 4);
        pre2[e] = *(const float4*)(A + (size_t)(row0 + m) * KDIM + 32 + pkq * 4);
    }

    for (int ch = 0; ch < NCH; ch++) {
        const int st  = ch & 1;
        const int use = ch >> 1;
        if (use >= 1) { MBARRIER_WAIT_PARITY(mbA[st], (use - 1) & 1); }

        char* ps = bp + st * STAGE_SZ;
        const int k0 = ch * 32;

        {
            const uint32_t dstA = sbu + st * STAGE_SZ + 32768;
#pragma unroll
            for (int cb = 0; cb < 2; cb++) {
                const float4* src = (const float4*)(wt + (size_t)(cb * NCH + ch) * 8192);
#pragma unroll
                for (int i = 0; i < 4; i++) {
                    asm volatile("cp.async.cg.shared.global [%0], [%1], 16;"
                                 :: "r"(dstA + (uint32_t)cb * 32768u + (uint32_t)(tid + i * 512) * 16),
                                    "l"(src + tid + i * 512) : "memory");
                }
            }
            asm volatile("cp.async.commit_group;" ::: "memory");
        }

        float4 nxt[2];
        if (ch + 2 < NCH) {
            const int k2 = (ch + 2) * 32;
#pragma unroll
            for (int e = 0; e < 2; e++) {
                int m = (tid + e * 512) >> 3;
                nxt[e] = *(const float4*)(A + (size_t)(row0 + m) * KDIM + k2 + pkq * 4);
            }
        }

        {
            char* pAh = ps;
            char* pAl = ps + 16384;
#pragma unroll
            for (int e = 0; e < 2; e++) {
                int m = (tid + e * 512) >> 3;
                float4 v4 = pre[e];
                float vv[4] = {v4.x, v4.y, v4.z, v4.w};
                uint32_t hi[4]; float lo[4];
#pragma unroll
                for (int u = 0; u < 4; u++) {
                    float v = vv[u];
                    int k = k0 + pkq * 4 + u;
                    v = fmaf(v, sSc[k], sSh[k]);
                    v = v > 0.f ? v : 0.2f * v;
                    asm("cvt.rna.tf32.f32 %0, %1;" : "=r"(hi[u]) : "f"(v));
                    lo[u] = v - __uint_as_float(hi[u]);
                }
                uint32_t off = SW128((uint32_t)(m * 128 + pkq * 16));
                *(uint4*)(pAh + off)  = make_uint4(hi[0], hi[1], hi[2], hi[3]);
                *(float4*)(pAl + off) = make_float4(lo[0], lo[1], lo[2], lo[3]);
            }
        }
        asm volatile("cp.async.wait_group 0;" ::: "memory");
        asm volatile("fence.proxy.async.shared::cta;" ::: "memory");
        __syncthreads();

        if (wid == 0 && elect1()) {
            const uint32_t sbase = sbu + st * STAGE_SZ;
            uint64_t adh = sdesc(sbase), adl = sdesc(sbase + 16384);
#pragma unroll
            for (int cb = 0; cb < 2; cb++) {
                uint64_t bdh = sdesc(sbase + 32768 + cb * 32768);
                uint64_t bdl = sdesc(sbase + 49152 + cb * 32768);
                uint32_t dofs = tmem + cb * 128;
#pragma unroll
                for (int ks = 0; ks < 4; ks++) {
                    uint32_t en0 = (ch == 0 && ks == 0) ? 0u : 1u;
                    mma_tf32_ss(dofs, adh + ks * 2, bdh + ks * 2, IDESC_TF32, en0);
                    mma_tf32_ss(dofs, adh + ks * 2, bdl + ks * 2, IDESC_TF32, 1u);
                    mma_tf32_ss(dofs, adl + ks * 2, bdh + ks * 2, IDESC_TF32, 1u);
                }
            }
            TCGEN05_COMMIT(mbA[st]);
        }
        pre[0] = pre2[0]; pre[1] = pre2[1];
        pre2[0] = nxt[0]; pre2[1] = nxt[1];
    }
    MBARRIER_WAIT_PARITY(mbA[(NCH - 1) & 1], ((NCH - 1) >> 1) & 1);
    TCGEN05_FENCE_AFTER();
    __syncthreads();

    {
        const int wg     = wid >> 2;
        const int rw     = wid & 3;
        const int wg_tid = tid & 127;
        const int cb = wg >> 1, h = wg & 1;
        const int bc = cb * 128 + h * 64;
        float* stage = (float*)(bp + wg * 36864);

#pragma unroll
        for (int half = 0; half < 2; half++) {
            uint32_t regs[32];
            TCGEN05_LD_32X32B_X32(regs, tmem + cb * 128 + h * 64 + half * 32);
            TCGEN05_WAIT_LD();
            const int row = rw * 32 + lane;
#pragma unroll
            for (int j4 = 0; j4 < 8; j4++) {
                int cc = half * 32 + j4 * 4;
                float4 v = make_float4(
                    __uint_as_float(regs[j4 * 4 + 0]) + sB[bc + cc + 0],
                    __uint_as_float(regs[j4 * 4 + 1]) + sB[bc + cc + 1],
                    __uint_as_float(regs[j4 * 4 + 2]) + sB[bc + cc + 2],
                    __uint_as_float(regs[j4 * 4 + 3]) + sB[bc + cc + 3]);
                *(float4*)(stage + row * 68 + cc) = v;
            }
        }
        TCGEN05_FENCE_BEFORE();
        asm volatile("bar.sync %0, 128;" :: "r"(wg + 1) : "memory");

        const int cq = wg_tid & 15;
        const int rg = wg_tid >> 4;
        float sA[4] = {0.f, 0.f, 0.f, 0.f};
        float qA[4] = {0.f, 0.f, 0.f, 0.f};
#pragma unroll 4
        for (int it = 0; it < 16; it++) {
            int r = it * 8 + rg;
            float4 v = *(const float4*)(stage + r * 68 + cq * 4);
            *(float4*)&C[(size_t)(row0 + r) * N + bc + cq * 4] = v;
            sA[0] += v.x; qA[0] = fmaf(v.x, v.x, qA[0]);
            sA[1] += v.y; qA[1] = fmaf(v.y, v.y, qA[1]);
            sA[2] += v.z; qA[2] = fmaf(v.z, v.z, qA[2]);
            sA[3] += v.w; qA[3] = fmaf(v.w, v.w, qA[3]);
        }
        *(float4*)&redS[(wg * 8 + rg) * 64 + cq * 4] = make_float4(sA[0], sA[1], sA[2], sA[3]);
        *(float4*)&redQ[(wg * 8 + rg) * 64 + cq * 4] = make_float4(qA[0], qA[1], qA[2], qA[3]);
        __syncthreads();
        if (tid < 256) {
            const int wgi = tid >> 6;
            const int colin = tid & 63;
            float s = 0.f, q = 0.f;
#pragma unroll
            for (int rr = 0; rr < 8; rr++) {
                s += redS[(wgi * 8 + rr) * 64 + colin];
                q += redQ[(wgi * 8 + rr) * 64 + colin];
            }
            g_psum[(size_t)tid * NPB2 + blockIdx.x] = s;
            g_psq [(size_t)tid * NPB2 + blockIdx.x] = q;
        }
    }

    __syncthreads();
    if (wid == 0) { TCGEN05_RELINQ(); TCGEN05_DEALLOC(tmem, 256); }

#else
    // FFMA fallback: 128 rows x 256 cols per CTA
    extern __shared__ char dsm[];
    float (*As)[128] = (float(*)[128])dsm;
    float (*Ws)[128] = (float(*)[128])(dsm + 8192);
    float* sSc = (float*)(dsm + 16384);
    float* sSh = (float*)(dsm + 17408);

    const int tid = threadIdx.x;
    for (int i = tid; i < KDIM; i += 512) { sSc[i] = g_scale[i]; sSh[i] = g_shift[i]; }
    __syncthreads();
    const int ty = tid >> 4;
    const int tx = tid & 15;
    const int row0 = blockIdx.x * 128;

#pragma unroll 1
    for (int cbk = 0; cbk < 2; cbk++) {
        const int col0 = cbk * 128;
        float bj[8];
#pragma unroll
        for (int j = 0; j < 8; j++) bj[j] = bias[col0 + tx * 8 + j];
        float cs[8], cq[8];
#pragma unroll
        for (int j = 0; j < 8; j++) { cs[j] = 0.f; cq[j] = 0.f; }

        float acc[4][8];
#pragma unroll
        for (int i = 0; i < 4; i++)
#pragma unroll
            for (int j = 0; j < 8; j++) acc[i][j] = 0.f;

        for (int k0 = 0; k0 < KDIM; k0 += 16) {
#pragma unroll
            for (int l = 0; l < 4; l++) {
                int idx = tid + l * 512;
                int m = idx >> 4, kk = idx & 15;
                int k = k0 + kk;
                float v = A[(size_t)(row0 + m) * KDIM + k];
                v = fmaf(v, sSc[k], sSh[k]);
                v = v > 0.f ? v : 0.2f * v;
                As[kk][m] = v;
            }
#pragma unroll
            for (int l = 0; l < 4; l++) {
                int idx = tid + l * 512;
                int kk = idx >> 7, n = idx & 127;
                int k = k0 + kk;
                Ws[kk][n] = W[(size_t)k * N + col0 + n];
            }
            __syncthreads();
#pragma unroll
            for (int kk = 0; kk < 16; kk++) {
                float4 a0 = *(const float4*)&As[kk][ty * 4];
                float4 w0 = *(const float4*)&Ws[kk][tx * 8];
                float4 w1 = *(const float4*)&Ws[kk][tx * 8 + 4];
                float a[4] = {a0.x, a0.y, a0.z, a0.w};
                float w[8] = {w0.x, w0.y, w0.z, w0.w, w1.x, w1.y, w1.z, w1.w};
#pragma unroll
                for (int i = 0; i < 4; i++)
#pragma unroll
                    for (int j = 0; j < 8; j++)
                        acc[i][j] = fmaf(a[i], w[j], acc[i][j]);
            }
            __syncthreads();
        }
#pragma unroll
        for (int i = 0; i < 4; i++) {
            float v[8];
#pragma unroll
            for (int j = 0; j < 8; j++) {
                v[j] = acc[i][j] + bj[j];
                cs[j] += v[j];
                cq[j] = fmaf(v[j], v[j], cq[j]);
            }
            float* cptr = &C[(size_t)(row0 + ty * 4 + i) * N + col0 + tx * 8];
            *(float4*)cptr       = make_float4(v[0], v[1], v[2], v[3]);
            *(float4*)(cptr + 4) = make_float4(v[4], v[5], v[6], v[7]);
        }
        __syncthreads();

        float* red = &As[0][0];
#pragma unroll
        for (int j = 0; j < 8; j++) red[ty * 128 + tx * 8 + j] = cs[j];
        __syncthreads();
        if (tid < 128) {
            float s = 0.f;
#pragma unroll
            for (int r = 0; r < 32; r++) s += red[r * 128 + tid];
            g_psum[(size_t)(col0 + tid) * NPB2 + blockIdx.x] = s;
        }
        __syncthreads();
#pragma unroll
        for (int j = 0; j < 8; j++) red[ty * 128 + tx * 8 + j] = cq[j];
        __syncthreads();
        if (tid < 128) {
            float s = 0.f;
#pragma unroll
            for (int r = 0; r < 32; r++) s += red[r * 128 + tid];
            g_psq[(size_t)(col0 + tid) * NPB2 + blockIdx.x] = s;
        }
        __syncthreads();
    }
#endif
}

// ---------------------------------------------------------------------------
__global__ void stats_kernel(const float* __restrict__ gamma,
                             const float* __restrict__ beta, int N, int npb)
{
    __shared__ float ss[128], qq[128];
    const int c = blockIdx.x;
    const int t = threadIdx.x;
    const float* bs = g_psum + (size_t)c * npb;
    const float* bq = g_psq  + (size_t)c * npb;
    float s = 0.f, q = 0.f;
    for (int r = t; r < npb; r += 128) { s += bs[r]; q += bq[r]; }
    ss[t] = s; qq[t] = q;
    __syncthreads();
    for (int off = 64; off > 0; off >>= 1) {
        if (t < off) { ss[t] += ss[t + off]; qq[t] += qq[t + off]; }
        __syncthreads();
    }
    if (t == 0) {
        float mean = ss[0] * (1.0f / (float)BATCH);
        float var  = qq[0] * (1.0f / (float)BATCH) - mean * mean;
        float inv  = rsqrtf(var + 1e-5f);
        float scl  = gamma[c] * inv;
        g_scale[c] = scl;
        g_shift[c] = beta[c] - mean * scl;
    }
}

// ---------------------------------------------------------------------------
// final: L4 GEMM + 15 rounds Gumbel argmax. 256 rows/block, 512 blocks,
// 2 CTAs/SM. THREE u staging buffers + wait_group 1: one full step-buffer
// always streaming during compute. Per-row math identical.
// smem floats: w4s 3200 | sc 128 | sh 128 | b4s 32 | outS 3840 |
//              us0/1/2 3x6400 => 26528 floats = 106112 B
// ---------------------------------------------------------------------------
#define FINAL_SMEM (104 * 1024)

__global__ __launch_bounds__(256, 2)
void final_kernel(const float* __restrict__ W4, const float* __restrict__ b4,
                  const float* __restrict__ U, float* __restrict__ out)
{
    extern __shared__ __align__(16) float fsm[];
    float* w4s  = fsm;               // 3200
    float* sc   = fsm + 3200;        // 128
    float* sh   = fsm + 3328;        // 128
    float* b4s  = fsm + 3456;        // 32
    float* outS = fsm + 3488;        // 3840
    float* us[3] = { fsm + 7328, fsm + 13728, fsm + 20128 };  // 6400 each

    const int tid  = threadIdx.x;
    const int row0 = blockIdx.x * 256;
    const int row  = row0 + tid;

    for (int i = tid; i < 3200; i += 256) w4s[i] = W4[i];
    if (tid < 25) b4s[tid] = b4[tid];
    if (tid < 128) { sc[tid] = g_scale[tid]; sh[tid] = g_shift[tid]; }

    const uint32_t usA[3] = { smem_u32(us[0]), smem_u32(us[1]), smem_u32(us[2]) };

    // prefetch steps 0 and 1 while computing logits
#pragma unroll
    for (int p = 0; p < 2; p++) {
        const float4* src = (const float4*)(U + ((size_t)p * BATCH + row0) * 25);
        for (int i = tid; i < 1600; i += 256) {
            asm volatile("cp.async.cg.shared.global [%0], [%1], 16;"
                         :: "r"(usA[p] + i * 16), "l"(src + i) : "memory");
        }
        asm volatile("cp.async.commit_group;" ::: "memory");
    }
    __syncthreads();

    float lgt[25];
#pragma unroll
    for (int j = 0; j < 25; j++) lgt[j] = b4s[j];

    const float* arow = g_a3 + (size_t)row * 128;
    for (int k = 0; k < 128; k += 4) {
        float4 a4 = *(const float4*)(arow + k);
        float hv[4] = {a4.x, a4.y, a4.z, a4.w};
#pragma unroll
        for (int t = 0; t < 4; t++) {
            float h = fmaf(hv[t], sc[k + t], sh[k + t]);
            h = h > 0.f ? h : 0.2f * h;
#pragma unroll
            for (int j = 0; j < 25; j++)
                lgt[j] = fmaf(h, w4s[(k + t) * 25 + j], lgt[j]);
        }
    }

    unsigned mask = 0x1FFFFFFu;
    int bufi = 0;
#pragma unroll 1
    for (int s = 0; s < 15; s++) {
        // oldest outstanding group = buffer for step s; allow 1 newer in flight
        asm volatile("cp.async.wait_group 1;" ::: "memory");
        __syncthreads();
        if (s < 13) {
            const int p = (bufi + 2) % 3;
            const float4* src = (const float4*)(U + ((size_t)(s + 2) * BATCH + row0) * 25);
            for (int i = tid; i < 1600; i += 256) {
                asm volatile("cp.async.cg.shared.global [%0], [%1], 16;"
                             :: "r"(usA[p] + i * 16), "l"(src + i) : "memory");
            }
            asm volatile("cp.async.commit_group;" ::: "memory");
        } else {
            asm volatile("cp.async.commit_group;" ::: "memory");  // empty group keeps counts uniform
        }
        const float* ub = us[bufi];

        float best = -CUDART_INF_F;
        int bi = __ffs(mask) - 1;
#pragma unroll
        for (int j = 0; j < 25; j++) {
            if (mask & (1u << j)) {
                float uu = ub[tid * 25 + j];
                float nz = -__logf(-__logf(uu));
                float v  = lgt[j] + nz;
                if (v > best) { best = v; bi = j; }
            }
        }
        mask &= ~(1u << bi);
        outS[tid * 15 + s] = (float)bi / 24.0f;
        bufi = (bufi + 1) % 3;
    }
    __syncthreads();
    {
        float4* dst = (float4*)(out + (size_t)row0 * 15);
        const float4* src = (const float4*)outS;
        for (int i = tid; i < 960; i += 256) dst[i] = src[i];
    }
}

// ---------------------------------------------------------------------------
extern "C" void kernel_launch(void* const* d_in, const int* in_sizes, int n_in,
                              void* d_out, int out_size)
{
    const float* z   = (const float*)d_in[0];
    const float* u   = (const float*)d_in[1];
    const float* W1  = (const float*)d_in[2];
    const float* b1  = (const float*)d_in[3];
    const float* g1  = (const float*)d_in[4];
    const float* be1 = (const float*)d_in[5];
    const float* W2  = (const float*)d_in[6];
    const float* b2  = (const float*)d_in[7];
    const float* g2  = (const float*)d_in[8];
    const float* be2 = (const float*)d_in[9];
    const float* W3  = (const float*)d_in[10];
    const float* b3  = (const float*)d_in[11];
    const float* g3  = (const float*)d_in[12];
    const float* be3 = (const float*)d_in[13];
    const float* W4  = (const float*)d_in[14];
    const float* b4  = (const float*)d_in[15];
    float* out = (float*)d_out;

    float *a1, *a2, *a3, *wt;
    cudaGetSymbolAddress((void**)&a1, g_a1);
    cudaGetSymbolAddress((void**)&a2, g_a2);
    cudaGetSymbolAddress((void**)&a3, g_a3);
    cudaGetSymbolAddress((void**)&wt, g_wtiles);
    float* wt1 = wt;            // L1: 2 tiles
    float* wt2 = wt + 16384;    // L2: 8 tiles
    float* wt3 = wt + 81920;    // L3: 8 tiles

    cudaFuncSetAttribute(gemm_tc<50,  false>, cudaFuncAttributeMaxDynamicSharedMemorySize, GEMM_SMEM);
    cudaFuncSetAttribute(gemm_wide,           cudaFuncAttributeMaxDynamicSharedMemorySize, GEMM_SMEM);
    cudaFuncSetAttribute(gemm_tc<256, true >, cudaFuncAttributeMaxDynamicSharedMemorySize, GEMM_SMEM);
    cudaFuncSetAttribute(final_kernel, cudaFuncAttributeMaxDynamicSharedMemorySize, FINAL_SMEM);

    prep_all<<<18, 256>>>(W1, W2, W3, wt);

    gemm_tc<50,  false><<<dim3(NPB, 1), 512, GEMM_SMEM>>>(z,  W1, wt1, b1, a1, 128);
    stats_kernel<<<128, 128>>>(g1, be1, 128, NPB);
    gemm_wide<<<dim3(NPB2, 1), 512, GEMM_SMEM>>>(a1, W2, wt2, b2, a2);
    stats_kernel<<<256, 128>>>(g2, be2, 256, NPB2);
    gemm_tc<256, true ><<<dim3(NPB, 1), 512, GEMM_SMEM>>>(a2, W3, wt3, b3, a3, 128);
    stats_kernel<<<128, 128>>>(g3, be3, 128, NPB);
    final_kernel<<<512, 256, FINAL_SMEM>>>(W4, b4, u, out);
}

// round 17
// speedup vs baseline: 1.1081x; 1.1081x over previous
#include <cuda_runtime.h>
#include <cstdint>
#include <math_constants.h>

#define BATCH 131072
#define RPB   256              /* rows per CTA (narrow gemm) */
#define NPB   (BATCH / RPB)    /* 512 row blocks (narrow) */
#define NPB2  1024             /* 128-row blocks (wide gemm) */

#if defined(__CUDA_ARCH_FEAT_SM103_ALL) || defined(__CUDA_ARCH_FEAT_SM100_ALL) || defined(__CUDA_ARCH_FEAT_SM101_ALL)
#define HAS_TCGEN05 1
#else
#define HAS_TCGEN05 0
#endif

// ---------------- scratch ----------------------------------------------------
__device__ float g_a1[BATCH * 128];
__device__ float g_a2[BATCH * 256];
__device__ float g_a3[BATCH * 128];
__device__ float g_psum[256 * NPB2];  // column-major: [col][rowblock]
__device__ float g_psq [256 * NPB2];
__device__ float g_scale[256];
__device__ float g_shift[256];
__device__ float g_wtiles[147456];    // preformatted W tiles (8192 floats each)

// ---------------- ptx helpers -------------------------------------------------
__device__ __forceinline__ uint32_t smem_u32(const void* p) {
    uint32_t a;
    asm("{ .reg .u64 t; cvta.to.shared.u64 t, %1; cvt.u32.u64 %0, t; }" : "=r"(a) : "l"(p));
    return a;
}

#if HAS_TCGEN05
__device__ __forceinline__ uint32_t elect1() {
    uint32_t p;
    asm volatile("{\n\t.reg .pred p;\n\telect.sync _|p, 0xFFFFFFFF;\n\tselp.b32 %0, 1, 0, p;\n\t}" : "=r"(p));
    return p;
}
#define TCGEN05_ALLOC(smem_addr, nCols) \
    asm volatile("tcgen05.alloc.cta_group::1.sync.aligned.shared::cta.b32 [%0], %1;" \
                 :: "r"((uint32_t)(smem_addr)), "r"((uint32_t)(nCols)) : "memory")
#define TCGEN05_DEALLOC(tmem_addr, nCols) \
    asm volatile("tcgen05.dealloc.cta_group::1.sync.aligned.b32 %0, %1;" \
                 :: "r"(tmem_addr), "r"((uint32_t)(nCols)))
#define TCGEN05_RELINQ() \
    asm volatile("tcgen05.relinquish_alloc_permit.cta_group::1.sync.aligned;")
#define TCGEN05_COMMIT(mbar_smem_addr) \
    asm volatile("tcgen05.commit.cta_group::1.mbarrier::arrive::one.shared::cluster.b64 [%0];" \
                 :: "r"((uint32_t)(mbar_smem_addr)) : "memory")
#define TCGEN05_FENCE_AFTER() \
    asm volatile("tcgen05.fence::after_thread_sync;" ::: "memory")
#define TCGEN05_FENCE_BEFORE() \
    asm volatile("tcgen05.fence::before_thread_sync;" ::: "memory")
#define TCGEN05_WAIT_LD() \
    asm volatile("tcgen05.wait::ld.sync.aligned;" ::: "memory")
#define MBARRIER_INIT(mbar_smem_addr, count) \
    asm volatile("mbarrier.init.shared.b64 [%0], %1;" \
                 :: "r"((uint32_t)(mbar_smem_addr)), "r"((uint32_t)(count)) : "memory")
#define MBARRIER_WAIT_PARITY(mbar_smem_addr, phase_parity) do { \
    uint32_t _mbar = (uint32_t)(mbar_smem_addr); \
    uint32_t _parity = (uint32_t)(phase_parity); \
    uint32_t _done; \
    asm volatile("{\n\t.reg .pred p;\n\t" \
        "mbarrier.try_wait.parity.acquire.cta.shared::cta.b64 p, [%1], %2;\n\t" \
        "selp.b32 %0, 1, 0, p;\n\t}" \
        : "=r"(_done) : "r"(_mbar), "r"(_parity) : "memory"); \
    if (!_done) { \
        asm volatile("{\n\t.reg .pred P1;\n\t" \
            "WAIT_LOOP_%=:\n\t" \
            "mbarrier.try_wait.parity.acquire.cta.shared::cta.b64 P1, [%0], %1, 0x989680;\n\t" \
            "@P1 bra.uni WAIT_DONE_%=;\n\t" \
            "bra.uni WAIT_LOOP_%=;\n\t" \
            "WAIT_DONE_%=:\n\t}" \
            :: "r"(_mbar), "r"(_parity) : "memory"); \
    } \
} while (0)
#define TCGEN05_LD_32X32B_X32(r, tmem_addr) \
    asm volatile("tcgen05.ld.sync.aligned.32x32b.x32.b32 " \
        "{%0, %1, %2, %3, %4, %5, %6, %7, " \
        " %8, %9, %10, %11, %12, %13, %14, %15, " \
        " %16, %17, %18, %19, %20, %21, %22, %23, " \
        " %24, %25, %26, %27, %28, %29, %30, %31}, [%32];" \
        : "=r"((r)[0]),  "=r"((r)[1]),  "=r"((r)[2]),  "=r"((r)[3]), \
          "=r"((r)[4]),  "=r"((r)[5]),  "=r"((r)[6]),  "=r"((r)[7]), \
          "=r"((r)[8]),  "=r"((r)[9]),  "=r"((r)[10]), "=r"((r)[11]), \
          "=r"((r)[12]), "=r"((r)[13]), "=r"((r)[14]), "=r"((r)[15]), \
          "=r"((r)[16]), "=r"((r)[17]), "=r"((r)[18]), "=r"((r)[19]), \
          "=r"((r)[20]), "=r"((r)[21]), "=r"((r)[22]), "=r"((r)[23]), \
          "=r"((r)[24]), "=r"((r)[25]), "=r"((r)[26]), "=r"((r)[27]), \
          "=r"((r)[28]), "=r"((r)[29]), "=r"((r)[30]), "=r"((r)[31]) \
        : "r"(tmem_addr))

__device__ __forceinline__ uint64_t sdesc(uint32_t addr) {
    return ((uint64_t)2 << 61) | ((uint64_t)1 << 46) | ((uint64_t)64 << 32) |
           ((uint64_t)1 << 16) | ((uint64_t)(addr >> 4) & 0x3FFF);
}
__device__ __forceinline__ void mma_tf32_ss(uint32_t d, uint64_t ad, uint64_t bd,
                                            uint32_t idesc, uint32_t en) {
    asm volatile("{\n\t.reg .pred p;\n\tsetp.ne.u32 p, %4, 0;\n\t"
        "tcgen05.mma.cta_group::1.kind::tf32 [%0], %1, %2, %3, {%5, %5, %5, %5}, p;\n\t}"
        :: "r"(d), "l"(ad), "l"(bd), "r"(idesc), "r"(en), "r"(0u) : "memory");
}
#endif // HAS_TCGEN05

#define SW128(o) ((o) ^ (((o) >> 3) & 0x70))

#define STAGE_SZ 98304
#define GEMM_SMEM (216 * 1024)
#define IDESC_TF32 ((1u << 4) | (2u << 7) | (2u << 10) | (16u << 17) | (8u << 24))

// ---------------------------------------------------------------------------
// prep_all: one launch formats all W tiles (tf32 hi/lo split, SW128 image).
// ---------------------------------------------------------------------------
__global__ void prep_all(const float* __restrict__ W1, const float* __restrict__ W2,
                         const float* __restrict__ W3, float* __restrict__ wt)
{
    const int b = blockIdx.x;
    const float* W; float* dst; int Kdim, N, ch, cb, NCH;
    if (b < 2)       { W = W1; dst = wt;         Kdim = 50;  N = 128; NCH = 2; ch = b;             cb = 0; }
    else if (b < 10) { W = W2; dst = wt + 16384; Kdim = 128; N = 256; NCH = 4; ch = (b - 2) & 3;   cb = (b - 2) >> 2; }
    else             { W = W3; dst = wt + 81920; Kdim = 256; N = 128; NCH = 8; ch = b - 10;        cb = 0; }

    char* tile = (char*)(dst + (size_t)(cb * NCH + ch) * 8192);
    const int tid = threadIdx.x;
#pragma unroll
    for (int e = 0; e < 16; e++) {
        int idx = tid + e * 256;
        int n = idx >> 5, kk = idx & 31;
        int k = ch * 32 + kk;
        float v = (k < Kdim) ? W[(size_t)k * N + cb * 128 + n] : 0.f;
        uint32_t hb; asm("cvt.rna.tf32.f32 %0, %1;" : "=r"(hb) : "f"(v));
        float lo = v - __uint_as_float(hb);
        uint32_t off = SW128((uint32_t)(n * 128 + kk * 4));
        *(uint32_t*)(tile + off)         = hb;
        *(float*)   (tile + 16384 + off) = lo;
    }
}

// ---------------------------------------------------------------------------
// Narrow GEMM (R15): M=256/CTA, N=128. Layers 1 & 3. Natural block order.
// ---------------------------------------------------------------------------
template<int KDIM, bool ACT>
__global__ __launch_bounds__(512, 1)
void gemm_tc(const float* __restrict__ A, const float* __restrict__ W,
             const float* __restrict__ wt, const float* __restrict__ bias,
             float* __restrict__ C, int N)
{
#if HAS_TCGEN05
    constexpr int NCH = (KDIM + 31) / 32;
    extern __shared__ char dsm[];
    const uint32_t sb0 = smem_u32(dsm);
    const uint32_t pad = ((sb0 + 1023) & ~1023u) - sb0;
    char* bp = dsm + pad;
    const uint32_t sbu = sb0 + pad;

    float* sSc  = (float*)(bp + 196608);
    float* sSh  = (float*)(bp + 197632);
    float* sB   = (float*)(bp + 198656);
    float* redS = (float*)(bp + 199680);
    float* redQ = (float*)(bp + 207872);

    __shared__ uint64_t s_mbar[2];
    __shared__ uint32_t s_tptr;
    const uint32_t mbA[2] = { smem_u32(&s_mbar[0]), smem_u32(&s_mbar[1]) };

    const int tid  = threadIdx.x;
    const int wid  = tid >> 5;
    const int lane = tid & 31;
    const int row0 = blockIdx.x * RPB;
    const int col0 = blockIdx.y * 128;

    if (ACT) {
        for (int i = tid; i < KDIM; i += 512) { sSc[i] = g_scale[i]; sSh[i] = g_shift[i]; }
    }
    for (int i = tid; i < 128; i += 512) sB[i] = bias[col0 + i];
    if (tid == 0) { MBARRIER_INIT(mbA[0], 1); MBARRIER_INIT(mbA[1], 1); }
    if (wid == 0) TCGEN05_ALLOC(smem_u32(&s_tptr), 256);
    __syncthreads();
    const uint32_t tmem = s_tptr;

    const int pkq = tid & 7;
    float4 pre[4];
    if (KDIM % 4 == 0) {
#pragma unroll
        for (int t = 0; t < 2; t++)
#pragma unroll
            for (int e = 0; e < 2; e++) {
                int m = (tid + e * 512) >> 3;
                pre[t * 2 + e] = *(const float4*)(A + (size_t)(row0 + t * 128 + m) * KDIM + pkq * 4);
            }
    }

    for (int ch = 0; ch < NCH; ch++) {
        const int st  = ch & 1;
        const int use = ch >> 1;
        if (use >= 1) { MBARRIER_WAIT_PARITY(mbA[st], (use - 1) & 1); }

        char* ps = bp + st * STAGE_SZ;
        const int k0 = ch * 32;

        {
            const float4* src = (const float4*)(wt + (size_t)(blockIdx.y * NCH + ch) * 8192);
            const uint32_t dstA = sbu + st * STAGE_SZ + 65536;
#pragma unroll
            for (int i = 0; i < 4; i++) {
                asm volatile("cp.async.cg.shared.global [%0], [%1], 16;"
                             :: "r"(dstA + (uint32_t)(tid + i * 512) * 16),
                                "l"(src + tid + i * 512) : "memory");
            }
            asm volatile("cp.async.commit_group;" ::: "memory");
        }

        float4 nxt[4];
        if (KDIM % 4 == 0 && ch + 1 < NCH) {
            const int k1 = (ch + 1) * 32;
#pragma unroll
            for (int t = 0; t < 2; t++)
#pragma unroll
                for (int e = 0; e < 2; e++) {
                    int m = (tid + e * 512) >> 3;
                    nxt[t * 2 + e] = *(const float4*)(A + (size_t)(row0 + t * 128 + m) * KDIM + k1 + pkq * 4);
                }
        }

        if (KDIM % 4 == 0) {
#pragma unroll
            for (int t = 0; t < 2; t++) {
                char* pAh = ps + t * 32768;
                char* pAl = pAh + 16384;
#pragma unroll
                for (int e = 0; e < 2; e++) {
                    int m = (tid + e * 512) >> 3;
                    float4 v4 = pre[t * 2 + e];
                    float vv[4] = {v4.x, v4.y, v4.z, v4.w};
                    uint32_t hi[4]; float lo[4];
#pragma unroll
                    for (int u = 0; u < 4; u++) {
                        float v = vv[u];
                        if (ACT) {
                            int k = k0 + pkq * 4 + u;
                            v = fmaf(v, sSc[k], sSh[k]);
                            v = v > 0.f ? v : 0.2f * v;
                        }
                        asm("cvt.rna.tf32.f32 %0, %1;" : "=r"(hi[u]) : "f"(v));
                        lo[u] = v - __uint_as_float(hi[u]);
                    }
                    uint32_t off = SW128((uint32_t)(m * 128 + pkq * 16));
                    *(uint4*)(pAh + off)  = make_uint4(hi[0], hi[1], hi[2], hi[3]);
                    *(float4*)(pAl + off) = make_float4(lo[0], lo[1], lo[2], lo[3]);
                }
            }
        } else {
#pragma unroll
            for (int t = 0; t < 2; t++) {
                char* pAh = ps + t * 32768;
                char* pAl = pAh + 16384;
                const int rbase = row0 + t * 128;
#pragma unroll
                for (int i = 0; i < 8; i++) {
                    int idx = tid + i * 512;
                    int m = idx >> 5, kk = idx & 31, k = k0 + kk;
                    float v = 0.f;
                    if (k < KDIM) {
                        v = A[(size_t)(rbase + m) * KDIM + k];
                        if (ACT) {
                            v = fmaf(v, sSc[k], sSh[k]);
                            v = v > 0.f ? v : 0.2f * v;
                        }
                    }
                    uint32_t hb; asm("cvt.rna.tf32.f32 %0, %1;" : "=r"(hb) : "f"(v));
                    float lo = v - __uint_as_float(hb);
                    uint32_t off = SW128((uint32_t)(m * 128 + kk * 4));
                    *(uint32_t*)(pAh + off) = hb;
                    *(float*)   (pAl + off) = lo;
                }
            }
        }
        asm volatile("cp.async.wait_group 0;" ::: "memory");
        asm volatile("fence.proxy.async.shared::cta;" ::: "memory");
        __syncthreads();

        if (wid == 0 && elect1()) {
            const uint32_t sbase = sbu + st * STAGE_SZ;
            uint64_t bdh = sdesc(sbase + 65536), bdl = sdesc(sbase + 81920);
#pragma unroll
            for (int t = 0; t < 2; t++) {
                uint64_t adh = sdesc(sbase + t * 32768);
                uint64_t adl = sdesc(sbase + t * 32768 + 16384);
                uint32_t dofs = tmem + t * 128;
#pragma unroll
                for (int ks = 0; ks < 4; ks++) {
                    uint32_t en0 = (ch == 0 && ks == 0) ? 0u : 1u;
                    mma_tf32_ss(dofs, adh + ks * 2, bdh + ks * 2, IDESC_TF32, en0);
                    mma_tf32_ss(dofs, adh + ks * 2, bdl + ks * 2, IDESC_TF32, 1u);
                    mma_tf32_ss(dofs, adl + ks * 2, bdh + ks * 2, IDESC_TF32, 1u);
                }
            }
            TCGEN05_COMMIT(mbA[st]);
        }
#pragma unroll
        for (int i = 0; i < 4; i++) pre[i] = nxt[i];
    }
    MBARRIER_WAIT_PARITY(mbA[(NCH - 1) & 1], ((NCH - 1) >> 1) & 1);
    TCGEN05_FENCE_AFTER();
    __syncthreads();

    {
        const int wg     = wid >> 2;
        const int rw     = wid & 3;
        const int wg_tid = tid & 127;
        const int t = wg >> 1, h = wg & 1;
        float* stage = (float*)(bp + wg * 36864);

#pragma unroll
        for (int half = 0; half < 2; half++) {
            uint32_t regs[32];
            TCGEN05_LD_32X32B_X32(regs, tmem + t * 128 + h * 64 + half * 32);
            TCGEN05_WAIT_LD();
            const int row = rw * 32 + lane;
#pragma unroll
            for (int j4 = 0; j4 < 8; j4++) {
                int cb = half * 32 + j4 * 4;
                float4 v = make_float4(
                    __uint_as_float(regs[j4 * 4 + 0]) + sB[h * 64 + cb + 0],
                    __uint_as_float(regs[j4 * 4 + 1]) + sB[h * 64 + cb + 1],
                    __uint_as_float(regs[j4 * 4 + 2]) + sB[h * 64 + cb + 2],
                    __uint_as_float(regs[j4 * 4 + 3]) + sB[h * 64 + cb + 3]);
                *(float4*)(stage + row * 68 + cb) = v;
            }
        }
        TCGEN05_FENCE_BEFORE();
        asm volatile("bar.sync %0, 128;" :: "r"(wg + 1) : "memory");

        const int cq = wg_tid & 15;
        const int rg = wg_tid >> 4;
        float sA[4] = {0.f, 0.f, 0.f, 0.f};
        float qA[4] = {0.f, 0.f, 0.f, 0.f};
#pragma unroll 4
        for (int it = 0; it < 16; it++) {
            int r = it * 8 + rg;
            float4 v = *(const float4*)(stage + r * 68 + cq * 4);
            *(float4*)&C[(size_t)(row0 + t * 128 + r) * N + col0 + h * 64 + cq * 4] = v;
            sA[0] += v.x; qA[0] = fmaf(v.x, v.x, qA[0]);
            sA[1] += v.y; qA[1] = fmaf(v.y, v.y, qA[1]);
            sA[2] += v.z; qA[2] = fmaf(v.z, v.z, qA[2]);
            sA[3] += v.w; qA[3] = fmaf(v.w, v.w, qA[3]);
        }
        *(float4*)&redS[(wg * 8 + rg) * 64 + cq * 4] = make_float4(sA[0], sA[1], sA[2], sA[3]);
        *(float4*)&redQ[(wg * 8 + rg) * 64 + cq * 4] = make_float4(qA[0], qA[1], qA[2], qA[3]);
        __syncthreads();
        if (tid < 128) {
            const int hh = tid >> 6, colin = tid & 63;
            float s = 0.f, q = 0.f;
#pragma unroll
            for (int tt = 0; tt < 2; tt++) {
                const int wgi = tt * 2 + hh;
#pragma unroll
                for (int rr = 0; rr < 8; rr++) {
                    s += redS[(wgi * 8 + rr) * 64 + colin];
                    q += redQ[(wgi * 8 + rr) * 64 + colin];
                }
            }
            int c = col0 + tid;
            g_psum[(size_t)c * NPB + blockIdx.x] = s;
            g_psq [(size_t)c * NPB + blockIdx.x] = q;
        }
    }

    __syncthreads();
    if (wid == 0) { TCGEN05_RELINQ(); TCGEN05_DEALLOC(tmem, 256); }

#else
    // FFMA fallback (plain sm_103 pass)
    extern __shared__ char dsm[];
    float (*As)[128] = (float(*)[128])dsm;
    float (*Ws)[128] = (float(*)[128])(dsm + 8192);
    float* sSc = (float*)(dsm + 16384);
    float* sSh = (float*)(dsm + 17408);

    const int tid  = threadIdx.x;
    const int col0 = blockIdx.y * 128;

    if (ACT) {
        for (int i = tid; i < KDIM; i += 512) { sSc[i] = g_scale[i]; sSh[i] = g_shift[i]; }
        __syncthreads();
    }
    const int ty = tid >> 4;
    const int tx = tid & 15;
    float bj[8];
#pragma unroll
    for (int j = 0; j < 8; j++) bj[j] = bias[col0 + tx * 8 + j];

    float cs[8], cq[8];
#pragma unroll
    for (int j = 0; j < 8; j++) { cs[j] = 0.f; cq[j] = 0.f; }

#pragma unroll 1
    for (int rt = 0; rt < 2; rt++) {
        const int row0 = blockIdx.x * RPB + rt * 128;
        float acc[4][8];
#pragma unroll
        for (int i = 0; i < 4; i++)
#pragma unroll
            for (int j = 0; j < 8; j++) acc[i][j] = 0.f;

        for (int k0 = 0; k0 < KDIM; k0 += 16) {
#pragma unroll
            for (int l = 0; l < 4; l++) {
                int idx = tid + l * 512;
                int m = idx >> 4, kk = idx & 15;
                int k = k0 + kk;
                float v = 0.f;
                if ((KDIM % 16 == 0) || k < KDIM) {
                    v = A[(size_t)(row0 + m) * KDIM + k];
                    if (ACT) {
                        v = fmaf(v, sSc[k], sSh[k]);
                        v = v > 0.f ? v : 0.2f * v;
                    }
                }
                As[kk][m] = v;
            }
#pragma unroll
            for (int l = 0; l < 4; l++) {
                int idx = tid + l * 512;
                int kk = idx >> 7, n = idx & 127;
                int k = k0 + kk;
                Ws[kk][n] = ((KDIM % 16 == 0) || k < KDIM) ? W[(size_t)k * N + col0 + n] : 0.f;
            }
            __syncthreads();
#pragma unroll
            for (int kk = 0; kk < 16; kk++) {
                float4 a0 = *(const float4*)&As[kk][ty * 4];
                float4 w0 = *(const float4*)&Ws[kk][tx * 8];
                float4 w1 = *(const float4*)&Ws[kk][tx * 8 + 4];
                float a[4] = {a0.x, a0.y, a0.z, a0.w};
                float w[8] = {w0.x, w0.y, w0.z, w0.w, w1.x, w1.y, w1.z, w1.w};
#pragma unroll
                for (int i = 0; i < 4; i++)
#pragma unroll
                    for (int j = 0; j < 8; j++)
                        acc[i][j] = fmaf(a[i], w[j], acc[i][j]);
            }
            __syncthreads();
        }
#pragma unroll
        for (int i = 0; i < 4; i++) {
            float v[8];
#pragma unroll
            for (int j = 0; j < 8; j++) {
                v[j] = acc[i][j] + bj[j];
                cs[j] += v[j];
                cq[j] = fmaf(v[j], v[j], cq[j]);
            }
            float* cptr = &C[(size_t)(row0 + ty * 4 + i) * N + col0 + tx * 8];
            *(float4*)cptr       = make_float4(v[0], v[1], v[2], v[3]);
            *(float4*)(cptr + 4) = make_float4(v[4], v[5], v[6], v[7]);
        }
        __syncthreads();
    }

    float* red = &As[0][0];
#pragma unroll
    for (int j = 0; j < 8; j++) red[ty * 128 + tx * 8 + j] = cs[j];
    __syncthreads();
    if (tid < 128) {
        float s = 0.f;
#pragma unroll
        for (int r = 0; r < 32; r++) s += red[r * 128 + tid];
        g_psum[(size_t)(col0 + tid) * NPB + blockIdx.x] = s;
    }
    __syncthreads();
#pragma unroll
    for (int j = 0; j < 8; j++) red[ty * 128 + tx * 8 + j] = cq[j];
    __syncthreads();
    if (tid < 128) {
        float s = 0.f;
#pragma unroll
        for (int r = 0; r < 32; r++) s += red[r * 128 + tid];
        g_psq[(size_t)(col0 + tid) * NPB + blockIdx.x] = s;
    }
#endif
}

// ---------------------------------------------------------------------------
// Wide GEMM (layer 2, R13/R15): M=128, N=256 per CTA, REVERSED block order
// (reads a1 rows that gemm1 wrote last -> L2 hot; leaves a2 low rows hot
// for gemm3's natural order).
// ---------------------------------------------------------------------------
__global__ __launch_bounds__(512, 1)
void gemm_wide(const float* __restrict__ A, const float* __restrict__ W,
               const float* __restrict__ wt, const float* __restrict__ bias,
               float* __restrict__ C)
{
    constexpr int KDIM = 128;
    constexpr int NCH  = 4;
    constexpr int N    = 256;
#if HAS_TCGEN05
    extern __shared__ char dsm[];
    const uint32_t sb0 = smem_u32(dsm);
    const uint32_t pad = ((sb0 + 1023) & ~1023u) - sb0;
    char* bp = dsm + pad;
    const uint32_t sbu = sb0 + pad;

    float* sSc  = (float*)(bp + 196608);
    float* sSh  = (float*)(bp + 197632);
    float* sB   = (float*)(bp + 198656);
    float* redS = (float*)(bp + 199680);
    float* redQ = (float*)(bp + 207872);

    __shared__ uint64_t s_mbar[2];
    __shared__ uint32_t s_tptr;
    const uint32_t mbA[2] = { smem_u32(&s_mbar[0]), smem_u32(&s_mbar[1]) };

    const int tid  = threadIdx.x;
    const int wid  = tid >> 5;
    const int lane = tid & 31;
    const int rb   = (int)gridDim.x - 1 - (int)blockIdx.x;   // reversed row block
    const int row0 = rb * 128;

    for (int i = tid; i < KDIM; i += 512) { sSc[i] = g_scale[i]; sSh[i] = g_shift[i]; }
    for (int i = tid; i < 256; i += 512) sB[i] = bias[i];
    if (tid == 0) { MBARRIER_INIT(mbA[0], 1); MBARRIER_INIT(mbA[1], 1); }
    if (wid == 0) TCGEN05_ALLOC(smem_u32(&s_tptr), 256);
    __syncthreads();
    const uint32_t tmem = s_tptr;

    const int pkq = tid & 7;
    float4 pre[2];
#pragma unroll
    for (int e = 0; e < 2; e++) {
        int m = (tid + e * 512) >> 3;
        pre[e] = *(const float4*)(A + (size_t)(row0 + m) * KDIM + pkq * 4);
    }

    for (int ch = 0; ch < NCH; ch++) {
        const int st  = ch & 1;
        const int use = ch >> 1;
        if (use >= 1) { MBARRIER_WAIT_PARITY(mbA[st], (use - 1) & 1); }

        char* ps = bp + st * STAGE_SZ;
        const int k0 = ch * 32;

        {
            const uint32_t dstA = sbu + st * STAGE_SZ + 32768;
#pragma unroll
            for (int cb = 0; cb < 2; cb++) {
                const float4* src = (const float4*)(wt + (size_t)(cb * NCH + ch) * 8192);
#pragma unroll
                for (int i = 0; i < 4; i++) {
                    asm volatile("cp.async.cg.shared.global [%0], [%1], 16;"
                                 :: "r"(dstA + (uint32_t)cb * 32768u + (uint32_t)(tid + i * 512) * 16),
                                    "l"(src + tid + i * 512) : "memory");
                }
            }
            asm volatile("cp.async.commit_group;" ::: "memory");
        }

        float4 nxt[2];
        if (ch + 1 < NCH) {
            const int k1 = (ch + 1) * 32;
#pragma unroll
            for (int e = 0; e < 2; e++) {
                int m = (tid + e * 512) >> 3;
                nxt[e] = *(const float4*)(A + (size_t)(row0 + m) * KDIM + k1 + pkq * 4);
            }
        }

        {
            char* pAh = ps;
            char* pAl = ps + 16384;
#pragma unroll
            for (int e = 0; e < 2; e++) {
                int m = (tid + e * 512) >> 3;
                float4 v4 = pre[e];
                float vv[4] = {v4.x, v4.y, v4.z, v4.w};
                uint32_t hi[4]; float lo[4];
#pragma unroll
                for (int u = 0; u < 4; u++) {
                    float v = vv[u];
                    int k = k0 + pkq * 4 + u;
                    v = fmaf(v, sSc[k], sSh[k]);
                    v = v > 0.f ? v : 0.2f * v;
                    asm("cvt.rna.tf32.f32 %0, %1;" : "=r"(hi[u]) : "f"(v));
                    lo[u] = v - __uint_as_float(hi[u]);
                }
                uint32_t off = SW128((uint32_t)(m * 128 + pkq * 16));
                *(uint4*)(pAh + off)  = make_uint4(hi[0], hi[1], hi[2], hi[3]);
                *(float4*)(pAl + off) = make_float4(lo[0], lo[1], lo[2], lo[3]);
            }
        }
        asm volatile("cp.async.wait_group 0;" ::: "memory");
        asm volatile("fence.proxy.async.shared::cta;" ::: "memory");
        __syncthreads();

        if (wid == 0 && elect1()) {
            const uint32_t sbase = sbu + st * STAGE_SZ;
            uint64_t adh = sdesc(sbase), adl = sdesc(sbase + 16384);
#pragma unroll
            for (int cb = 0; cb < 2; cb++) {
                uint64_t bdh = sdesc(sbase + 32768 + cb * 32768);
                uint64_t bdl = sdesc(sbase + 49152 + cb * 32768);
                uint32_t dofs = tmem + cb * 128;
#pragma unroll
                for (int ks = 0; ks < 4; ks++) {
                    uint32_t en0 = (ch == 0 && ks == 0) ? 0u : 1u;
                    mma_tf32_ss(dofs, adh + ks * 2, bdh + ks * 2, IDESC_TF32, en0);
                    mma_tf32_ss(dofs, adh + ks * 2, bdl + ks * 2, IDESC_TF32, 1u);
                    mma_tf32_ss(dofs, adl + ks * 2, bdh + ks * 2, IDESC_TF32, 1u);
                }
            }
            TCGEN05_COMMIT(mbA[st]);
        }
        pre[0] = nxt[0]; pre[1] = nxt[1];
    }
    MBARRIER_WAIT_PARITY(mbA[(NCH - 1) & 1], ((NCH - 1) >> 1) & 1);
    TCGEN05_FENCE_AFTER();
    __syncthreads();

    {
        const int wg     = wid >> 2;
        const int rw     = wid & 3;
        const int wg_tid = tid & 127;
        const int cb = wg >> 1, h = wg & 1;
        const int bc = cb * 128 + h * 64;
        float* stage = (float*)(bp + wg * 36864);

#pragma unroll
        for (int half = 0; half < 2; half++) {
            uint32_t regs[32];
            TCGEN05_LD_32X32B_X32(regs, tmem + cb * 128 + h * 64 + half * 32);
            TCGEN05_WAIT_LD();
            const int row = rw * 32 + lane;
#pragma unroll
            for (int j4 = 0; j4 < 8; j4++) {
                int cc = half * 32 + j4 * 4;
                float4 v = make_float4(
                    __uint_as_float(regs[j4 * 4 + 0]) + sB[bc + cc + 0],
                    __uint_as_float(regs[j4 * 4 + 1]) + sB[bc + cc + 1],
                    __uint_as_float(regs[j4 * 4 + 2]) + sB[bc + cc + 2],
                    __uint_as_float(regs[j4 * 4 + 3]) + sB[bc + cc + 3]);
                *(float4*)(stage + row * 68 + cc) = v;
            }
        }
        TCGEN05_FENCE_BEFORE();
        asm volatile("bar.sync %0, 128;" :: "r"(wg + 1) : "memory");

        const int cq = wg_tid & 15;
        const int rg = wg_tid >> 4;
        float sA[4] = {0.f, 0.f, 0.f, 0.f};
        float qA[4] = {0.f, 0.f, 0.f, 0.f};
#pragma unroll 4
        for (int it = 0; it < 16; it++) {
            int r = it * 8 + rg;
            float4 v = *(const float4*)(stage + r * 68 + cq * 4);
            *(float4*)&C[(size_t)(row0 + r) * N + bc + cq * 4] = v;
            sA[0] += v.x; qA[0] = fmaf(v.x, v.x, qA[0]);
            sA[1] += v.y; qA[1] = fmaf(v.y, v.y, qA[1]);
            sA[2] += v.z; qA[2] = fmaf(v.z, v.z, qA[2]);
            sA[3] += v.w; qA[3] = fmaf(v.w, v.w, qA[3]);
        }
        *(float4*)&redS[(wg * 8 + rg) * 64 + cq * 4] = make_float4(sA[0], sA[1], sA[2], sA[3]);
        *(float4*)&redQ[(wg * 8 + rg) * 64 + cq * 4] = make_float4(qA[0], qA[1], qA[2], qA[3]);
        __syncthreads();
        if (tid < 256) {
            const int wgi = tid >> 6;
            const int colin = tid & 63;
            float s = 0.f, q = 0.f;
#pragma unroll
            for (int rr = 0; rr < 8; rr++) {
                s += redS[(wgi * 8 + rr) * 64 + colin];
                q += redQ[(wgi * 8 + rr) * 64 + colin];
            }
            g_psum[(size_t)tid * NPB2 + rb] = s;
            g_psq [(size_t)tid * NPB2 + rb] = q;
        }
    }

    __syncthreads();
    if (wid == 0) { TCGEN05_RELINQ(); TCGEN05_DEALLOC(tmem, 256); }

#else
    // FFMA fallback: 128 rows x 256 cols per CTA (reversed order)
    extern __shared__ char dsm[];
    float (*As)[128] = (float(*)[128])dsm;
    float (*Ws)[128] = (float(*)[128])(dsm + 8192);
    float* sSc = (float*)(dsm + 16384);
    float* sSh = (float*)(dsm + 17408);

    const int tid = threadIdx.x;
    for (int i = tid; i < KDIM; i += 512) { sSc[i] = g_scale[i]; sSh[i] = g_shift[i]; }
    __syncthreads();
    const int ty = tid >> 4;
    const int tx = tid & 15;
    const int rb = (int)gridDim.x - 1 - (int)blockIdx.x;
    const int row0 = rb * 128;

#pragma unroll 1
    for (int cbk = 0; cbk < 2; cbk++) {
        const int col0 = cbk * 128;
        float bj[8];
#pragma unroll
        for (int j = 0; j < 8; j++) bj[j] = bias[col0 + tx * 8 + j];
        float cs[8], cq[8];
#pragma unroll
        for (int j = 0; j < 8; j++) { cs[j] = 0.f; cq[j] = 0.f; }

        float acc[4][8];
#pragma unroll
        for (int i = 0; i < 4; i++)
#pragma unroll
            for (int j = 0; j < 8; j++) acc[i][j] = 0.f;

        for (int k0 = 0; k0 < KDIM; k0 += 16) {
#pragma unroll
            for (int l = 0; l < 4; l++) {
                int idx = tid + l * 512;
                int m = idx >> 4, kk = idx & 15;
                int k = k0 + kk;
                float v = A[(size_t)(row0 + m) * KDIM + k];
                v = fmaf(v, sSc[k], sSh[k]);
                v = v > 0.f ? v : 0.2f * v;
                As[kk][m] = v;
            }
#pragma unroll
            for (int l = 0; l < 4; l++) {
                int idx = tid + l * 512;
                int kk = idx >> 7, n = idx & 127;
                int k = k0 + kk;
                Ws[kk][n] = W[(size_t)k * N + col0 + n];
            }
            __syncthreads();
#pragma unroll
            for (int kk = 0; kk < 16; kk++) {
                float4 a0 = *(const float4*)&As[kk][ty * 4];
                float4 w0 = *(const float4*)&Ws[kk][tx * 8];
                float4 w1 = *(const float4*)&Ws[kk][tx * 8 + 4];
                float a[4] = {a0.x, a0.y, a0.z, a0.w};
                float w[8] = {w0.x, w0.y, w0.z, w0.w, w1.x, w1.y, w1.z, w1.w};
#pragma unroll
                for (int i = 0; i < 4; i++)
#pragma unroll
                    for (int j = 0; j < 8; j++)
                        acc[i][j] = fmaf(a[i], w[j], acc[i][j]);
            }
            __syncthreads();
        }
#pragma unroll
        for (int i = 0; i < 4; i++) {
            float v[8];
#pragma unroll
            for (int j = 0; j < 8; j++) {
                v[j] = acc[i][j] + bj[j];
                cs[j] += v[j];
                cq[j] = fmaf(v[j], v[j], cq[j]);
            }
            float* cptr = &C[(size_t)(row0 + ty * 4 + i) * N + col0 + tx * 8];
            *(float4*)cptr       = make_float4(v[0], v[1], v[2], v[3]);
            *(float4*)(cptr + 4) = make_float4(v[4], v[5], v[6], v[7]);
        }
        __syncthreads();

        float* red = &As[0][0];
#pragma unroll
        for (int j = 0; j < 8; j++) red[ty * 128 + tx * 8 + j] = cs[j];
        __syncthreads();
        if (tid < 128) {
            float s = 0.f;
#pragma unroll
            for (int r = 0; r < 32; r++) s += red[r * 128 + tid];
            g_psum[(size_t)(col0 + tid) * NPB2 + rb] = s;
        }
        __syncthreads();
#pragma unroll
        for (int j = 0; j < 8; j++) red[ty * 128 + tx * 8 + j] = cq[j];
        __syncthreads();
        if (tid < 128) {
            float s = 0.f;
#pragma unroll
            for (int r = 0; r < 32; r++) s += red[r * 128 + tid];
            g_psq[(size_t)(col0 + tid) * NPB2 + rb] = s;
        }
        __syncthreads();
    }
#endif
}

// ---------------------------------------------------------------------------
__global__ void stats_kernel(const float* __restrict__ gamma,
                             const float* __restrict__ beta, int N, int npb)
{
    __shared__ float ss[128], qq[128];
    const int c = blockIdx.x;
    const int t = threadIdx.x;
    const float* bs = g_psum + (size_t)c * npb;
    const float* bq = g_psq  + (size_t)c * npb;
    float s = 0.f, q = 0.f;
    for (int r = t; r < npb; r += 128) { s += bs[r]; q += bq[r]; }
    ss[t] = s; qq[t] = q;
    __syncthreads();
    for (int off = 64; off > 0; off >>= 1) {
        if (t < off) { ss[t] += ss[t + off]; qq[t] += qq[t + off]; }
        __syncthreads();
    }
    if (t == 0) {
        float mean = ss[0] * (1.0f / (float)BATCH);
        float var  = qq[0] * (1.0f / (float)BATCH) - mean * mean;
        float inv  = rsqrtf(var + 1e-5f);
        float scl  = gamma[c] * inv;
        g_scale[c] = scl;
        g_shift[c] = beta[c] - mean * scl;
    }
}

// ---------------------------------------------------------------------------
// final (R15 + reversed block order): 256 rows/block, 512 blocks, 2 CTAs/SM,
// cp.async double-buffered u staging, coalesced out flush. Reads a3 rows
// that gemm3 wrote last first -> L2 hot.
// ---------------------------------------------------------------------------
#define FINAL_SMEM (82 * 1024)

__global__ __launch_bounds__(256, 2)
void final_kernel(const float* __restrict__ W4, const float* __restrict__ b4,
                  const float* __restrict__ U, float* __restrict__ out)
{
    extern __shared__ __align__(16) float fsm[];
    float* w4s  = fsm;               // 3200
    float* sc   = fsm + 3200;        // 128
    float* sh   = fsm + 3328;        // 128
    float* b4s  = fsm + 3456;        // 32
    float* outS = fsm + 3488;        // 3840
    float* us[2] = { fsm + 7328, fsm + 13728 };  // 6400 each

    const int tid  = threadIdx.x;
    const int rb   = (int)gridDim.x - 1 - (int)blockIdx.x;   // reversed
    const int row0 = rb * 256;
    const int row  = row0 + tid;

    for (int i = tid; i < 3200; i += 256) w4s[i] = W4[i];
    if (tid < 25) b4s[tid] = b4[tid];
    if (tid < 128) { sc[tid] = g_scale[tid]; sh[tid] = g_shift[tid]; }

    const uint32_t usA[2] = { smem_u32(us[0]), smem_u32(us[1]) };

    {
        const float4* src = (const float4*)(U + (size_t)row0 * 25);
        for (int i = tid; i < 1600; i += 256) {
            asm volatile("cp.async.cg.shared.global [%0], [%1], 16;"
                         :: "r"(usA[0] + i * 16), "l"(src + i) : "memory");
        }
        asm volatile("cp.async.commit_group;" ::: "memory");
    }
    __syncthreads();

    float lgt[25];
#pragma unroll
    for (int j = 0; j < 25; j++) lgt[j] = b4s[j];

    const float* arow = g_a3 + (size_t)row * 128;
    for (int k = 0; k < 128; k += 4) {
        float4 a4 = *(const float4*)(arow + k);
        float hv[4] = {a4.x, a4.y, a4.z, a4.w};
#pragma unroll
        for (int t = 0; t < 4; t++) {
            float h = fmaf(hv[t], sc[k + t], sh[k + t]);
            h = h > 0.f ? h : 0.2f * h;
#pragma unroll
            for (int j = 0; j < 25; j++)
                lgt[j] = fmaf(h, w4s[(k + t) * 25 + j], lgt[j]);
        }
    }

    unsigned mask = 0x1FFFFFFu;
#pragma unroll 1
    for (int s = 0; s < 15; s++) {
        asm volatile("cp.async.wait_group 0;" ::: "memory");
        __syncthreads();
        if (s < 14) {
            const float4* src = (const float4*)(U + ((size_t)(s + 1) * BATCH + row0) * 25);
            const uint32_t dst = usA[(s + 1) & 1];
            for (int i = tid; i < 1600; i += 256) {
                asm volatile("cp.async.cg.shared.global [%0], [%1], 16;"
                             :: "r"(dst + i * 16), "l"(src + i) : "memory");
            }
            asm volatile("cp.async.commit_group;" ::: "memory");
        }
        const float* ub = us[s & 1];

        float best = -CUDART_INF_F;
        int bi = __ffs(mask) - 1;
#pragma unroll
        for (int j = 0; j < 25; j++) {
            if (mask & (1u << j)) {
                float uu = ub[tid * 25 + j];
                float nz = -__logf(-__logf(uu));
                float v  = lgt[j] + nz;
                if (v > best) { best = v; bi = j; }
            }
        }
        mask &= ~(1u << bi);
        outS[tid * 15 + s] = (float)bi / 24.0f;
    }
    __syncthreads();
    {
        float4* dst = (float4*)(out + (size_t)row0 * 15);
        const float4* src = (const float4*)outS;
        for (int i = tid; i < 960; i += 256) dst[i] = src[i];
    }
}

// ---------------------------------------------------------------------------
extern "C" void kernel_launch(void* const* d_in, const int* in_sizes, int n_in,
                              void* d_out, int out_size)
{
    const float* z   = (const float*)d_in[0];
    const float* u   = (const float*)d_in[1];
    const float* W1  = (const float*)d_in[2];
    const float* b1  = (const float*)d_in[3];
    const float* g1  = (const float*)d_in[4];
    const float* be1 = (const float*)d_in[5];
    const float* W2  = (const float*)d_in[6];
    const float* b2  = (const float*)d_in[7];
    const float* g2  = (const float*)d_in[8];
    const float* be2 = (const float*)d_in[9];
    const float* W3  = (const float*)d_in[10];
    const float* b3  = (const float*)d_in[11];
    const float* g3  = (const float*)d_in[12];
    const float* be3 = (const float*)d_in[13];
    const float* W4  = (const float*)d_in[14];
    const float* b4  = (const float*)d_in[15];
    float* out = (float*)d_out;

    float *a1, *a2, *a3, *wt;
    cudaGetSymbolAddress((void**)&a1, g_a1);
    cudaGetSymbolAddress((void**)&a2, g_a2);
    cudaGetSymbolAddress((void**)&a3, g_a3);
    cudaGetSymbolAddress((void**)&wt, g_wtiles);
    float* wt1 = wt;            // L1: 2 tiles
    float* wt2 = wt + 16384;    // L2: 8 tiles
    float* wt3 = wt + 81920;    // L3: 8 tiles

    cudaFuncSetAttribute(gemm_tc<50,  false>, cudaFuncAttributeMaxDynamicSharedMemorySize, GEMM_SMEM);
    cudaFuncSetAttribute(gemm_wide,           cudaFuncAttributeMaxDynamicSharedMemorySize, GEMM_SMEM);
    cudaFuncSetAttribute(gemm_tc<256, true >, cudaFuncAttributeMaxDynamicSharedMemorySize, GEMM_SMEM);
    cudaFuncSetAttribute(final_kernel, cudaFuncAttributeMaxDynamicSharedMemorySize, FINAL_SMEM);

    prep_all<<<18, 256>>>(W1, W2, W3, wt);

    gemm_tc<50,  false><<<dim3(NPB, 1), 512, GEMM_SMEM>>>(z,  W1, wt1, b1, a1, 128);
    stats_kernel<<<128, 128>>>(g1, be1, 128, NPB);
    gemm_wide<<<dim3(NPB2, 1), 512, GEMM_SMEM>>>(a1, W2, wt2, b2, a2);
    stats_kernel<<<256, 128>>>(g2, be2, 256, NPB2);
    gemm_tc<256, true ><<<dim3(NPB, 1), 512, GEMM_SMEM>>>(a2, W3, wt3, b3, a3, 128);
    stats_kernel<<<128, 128>>>(g3, be3, 128, NPB);
    final_kernel<<<512, 256, FINAL_SMEM>>>(W4, b4, u, out);
}